// round 3
// baseline (speedup 1.0000x reference)
#include <cuda_runtime.h>
#include <math.h>

#define Bq  32
#define CDD 5
#define HIS 50
#define SS  20
#define EE  300
#define FF  150
#define KK  30
#define LL  3

// ---------------- scratch (static device globals; no allocs) ----------------
__device__ float  g_cdd_emb [Bq*CDD*SS*LL*FF];     // [bc][s][l][f]
__device__ float  g_his_emb [Bq*HIS*SS*LL*FF];     // [b*50+h][s][l][f]
__device__ double g_cdd_repr[Bq*CDD*FF];
__device__ double g_his_repr[Bq*HIS*FF];
__device__ int    g_topk    [Bq*CDD*KK];
__device__ float  g_fusion  [Bq*CDD*LL*KK*SS*SS];  // [bc][l][k][s][t]
__device__ float  g_pool1   [Bq*CDD*32*10*6*6];    // [bc][co][pd][ph][pw]
__device__ float  g_pool2   [Bq*CDD*192];          // [bc][co][d][h][w]

// load 20 consecutive smem floats via 5x LDS.128 into dst[off..off+19]
#define LOAD20(dst, src, off) { \
  const float4* _p = (const float4*)(src); \
  float4 _a=_p[0], _b=_p[1], _c=_p[2], _d=_p[3], _e=_p[4]; \
  (dst)[(off)+0]=_a.x; (dst)[(off)+1]=_a.y; (dst)[(off)+2]=_a.z; (dst)[(off)+3]=_a.w; \
  (dst)[(off)+4]=_b.x; (dst)[(off)+5]=_b.y; (dst)[(off)+6]=_b.z; (dst)[(off)+7]=_b.w; \
  (dst)[(off)+8]=_c.x; (dst)[(off)+9]=_c.y; (dst)[(off)+10]=_c.z; (dst)[(off)+11]=_c.w; \
  (dst)[(off)+12]=_d.x; (dst)[(off)+13]=_d.y; (dst)[(off)+14]=_d.z; (dst)[(off)+15]=_d.w; \
  (dst)[(off)+16]=_e.x; (dst)[(off)+17]=_e.y; (dst)[(off)+18]=_e.z; (dst)[(off)+19]=_e.w; }

// ---------------- encode: per-sequence fused conv stack + attention ---------
// dynamic smem layout (floats): xb 0..5999 | d1 6000 | d2 9000 | d3 12000 |
// mu 15000(20) | rs 15020(20) | lw 15040(60) | wwd 15104(double[20]=40 fl)
#define ENC_SMEM_FLOATS 15160
#define ENC_THREADS 160

// LayerNorm over f for each s, stats in fp64.
__device__ __forceinline__ void ln_T(float* buf, float* mu, float* rs,
                                     const float* lnw, const float* lnb, int tid) {
    __syncthreads();
    if (tid < SS) {
        double m = 0.0;
        for (int f = 0; f < FF; f++) m += (double)buf[f*SS + tid];
        m *= (1.0/FF);
        double v = 0.0;
        for (int f = 0; f < FF; f++) { double d = (double)buf[f*SS + tid] - m; v += d*d; }
        v *= (1.0/FF);
        mu[tid] = (float)m;
        rs[tid] = (float)(1.0 / sqrt(v + 1e-5));
    }
    __syncthreads();
    if (tid < FF) {
        float w = lnw[tid], b = lnb[tid];
        #pragma unroll
        for (int s = 0; s < SS; s++)
            buf[tid*SS + s] = (buf[tid*SS + s] - mu[s]) * rs[s] * w + b;
    }
    __syncthreads();
}

__global__ void __launch_bounds__(ENC_THREADS)
encode_kernel(const int* __restrict__ ids_all, const float* __restrict__ emb,
              const float* __restrict__ w1, const float* __restrict__ b1,
              const float* __restrict__ w2, const float* __restrict__ b2,
              const float* __restrict__ w3, const float* __restrict__ b3,
              const float* __restrict__ lnw, const float* __restrict__ lnb,
              const float* __restrict__ q_words, const float* __restrict__ q_levels,
              int is_his)
{
    extern __shared__ float sm[];
    float*  xb  = sm;            // [e][s]  6000
    float*  d1  = sm + 6000;     // [f][s]  3000
    float*  d2  = sm + 9000;
    float*  d3  = sm + 12000;
    float*  mu  = sm + 15000;
    float*  rs  = sm + 15020;
    float*  lw  = sm + 15040;    // [s][l] 60
    double* wwd = (double*)(sm + 15104); // [s] 20 doubles (8B aligned: 15104*4 % 8 == 0)
    float*  wfb = xb;            // reuse xb after conv1: wf [s][f] 3000
    __shared__ int ids[SS];

    const int seq = blockIdx.x;
    const int tid = threadIdx.x;

    float*  emb_out  = is_his ? g_his_emb  : g_cdd_emb;
    double* repr_out = is_his ? g_his_repr : g_cdd_repr;

    if (tid < SS) ids[tid] = ids_all[seq*SS + tid];
    __syncthreads();
    for (int i = tid; i < SS*EE; i += ENC_THREADS) {
        int s = i / EE, e = i % EE;
        xb[e*SS + s] = emb[(size_t)ids[s]*EE + e];
    }
    __syncthreads();

    // conv1: dilation 1, C_in=300. fp32 inner blocks of 25 ch, fp64 outer acc.
    if (tid < FF) {
        double accd[SS];
        double bv = (double)b1[tid];
        #pragma unroll
        for (int s = 0; s < SS; s++) accd[s] = bv;
        const float* wr = w1 + tid*(EE*3);
        for (int e0 = 0; e0 < EE; e0 += 25) {
            float acc[SS];
            #pragma unroll
            for (int s = 0; s < SS; s++) acc[s] = 0.f;
            for (int e = e0; e < e0 + 25; e++) {
                float xv[22]; xv[0] = 0.f; xv[21] = 0.f;
                LOAD20(xv, xb + e*SS, 1);
                float w0 = wr[e*3+0], wa = wr[e*3+1], wb = wr[e*3+2];
                #pragma unroll
                for (int s = 0; s < SS; s++)
                    acc[s] += w0*xv[s] + wa*xv[s+1] + wb*xv[s+2];
            }
            #pragma unroll
            for (int s = 0; s < SS; s++) accd[s] += (double)acc[s];
        }
        #pragma unroll
        for (int s = 0; s < SS; s++) d1[tid*SS + s] = (float)accd[s];
    }
    ln_T(d1, mu, rs, lnw, lnb, tid);

    // conv2: dilation 2, C_in=150
    if (tid < FF) {
        double accd[SS];
        double bv = (double)b2[tid];
        #pragma unroll
        for (int s = 0; s < SS; s++) accd[s] = bv;
        const float* wr = w2 + tid*(FF*3);
        for (int c0 = 0; c0 < FF; c0 += 25) {
            float acc[SS];
            #pragma unroll
            for (int s = 0; s < SS; s++) acc[s] = 0.f;
            for (int c = c0; c < c0 + 25; c++) {
                float dv[24]; dv[0]=0.f; dv[1]=0.f; dv[22]=0.f; dv[23]=0.f;
                LOAD20(dv, d1 + c*SS, 2);
                float w0 = wr[c*3+0], wa = wr[c*3+1], wb = wr[c*3+2];
                #pragma unroll
                for (int s = 0; s < SS; s++)
                    acc[s] += w0*dv[s] + wa*dv[s+2] + wb*dv[s+4];
            }
            #pragma unroll
            for (int s = 0; s < SS; s++) accd[s] += (double)acc[s];
        }
        #pragma unroll
        for (int s = 0; s < SS; s++) d2[tid*SS + s] = (float)accd[s];
    }
    ln_T(d2, mu, rs, lnw, lnb, tid);

    // conv3: dilation 3
    if (tid < FF) {
        double accd[SS];
        double bv = (double)b3[tid];
        #pragma unroll
        for (int s = 0; s < SS; s++) accd[s] = bv;
        const float* wr = w3 + tid*(FF*3);
        for (int c0 = 0; c0 < FF; c0 += 25) {
            float acc[SS];
            #pragma unroll
            for (int s = 0; s < SS; s++) acc[s] = 0.f;
            for (int c = c0; c < c0 + 25; c++) {
                float dv[26]; dv[0]=0.f; dv[1]=0.f; dv[2]=0.f; dv[23]=0.f; dv[24]=0.f; dv[25]=0.f;
                LOAD20(dv, d2 + c*SS, 3);
                float w0 = wr[c*3+0], wa = wr[c*3+1], wb = wr[c*3+2];
                #pragma unroll
                for (int s = 0; s < SS; s++)
                    acc[s] += w0*dv[s] + wa*dv[s+3] + wb*dv[s+6];
            }
            #pragma unroll
            for (int s = 0; s < SS; s++) accd[s] += (double)acc[s];
        }
        #pragma unroll
        for (int s = 0; s < SS; s++) d3[tid*SS + s] = (float)accd[s];
    }
    ln_T(d3, mu, rs, lnw, lnb, tid);

    const double inv_scale = 1.0 / sqrt((double)EE);

    // level attention: softmax over l per s (fp64 logits)
    if (tid < SS) {
        int s = tid;
        double l0 = 0.0, l1 = 0.0, l2 = 0.0;
        for (int f = 0; f < FF; f++) {
            double q = (double)q_levels[f];
            l0 += (double)fmaxf(d1[f*SS+s], 0.f) * q;
            l1 += (double)fmaxf(d2[f*SS+s], 0.f) * q;
            l2 += (double)fmaxf(d3[f*SS+s], 0.f) * q;
        }
        l0 *= inv_scale; l1 *= inv_scale; l2 *= inv_scale;
        double m = fmax(l0, fmax(l1, l2));
        double e0 = exp(l0-m), e1 = exp(l1-m), e2 = exp(l2-m);
        double inv = 1.0 / (e0+e1+e2);
        lw[s*3+0] = (float)(e0*inv); lw[s*3+1] = (float)(e1*inv); lw[s*3+2] = (float)(e2*inv);
    }
    __syncthreads();

    // wf[s][f]
    if (tid < FF) {
        #pragma unroll
        for (int s = 0; s < SS; s++) {
            float v = lw[s*3+0]*fmaxf(d1[tid*SS+s], 0.f)
                    + lw[s*3+1]*fmaxf(d2[tid*SS+s], 0.f)
                    + lw[s*3+2]*fmaxf(d3[tid*SS+s], 0.f);
            wfb[s*FF + tid] = v;
        }
    }
    __syncthreads();

    // word attention logits (fp64)
    if (tid < SS) {
        double g = 0.0;
        for (int f = 0; f < FF; f++) g += (double)wfb[tid*FF + f] * (double)q_words[f];
        wwd[tid] = g * inv_scale;
    }
    __syncthreads();
    if (tid == 0) {
        double m = -1e300;
        for (int s = 0; s < SS; s++) m = fmax(m, wwd[s]);
        double sum = 0.0;
        for (int s = 0; s < SS; s++) { double e = exp(wwd[s]-m); wwd[s] = e; sum += e; }
        double inv = 1.0 / sum;
        for (int s = 0; s < SS; s++) wwd[s] *= inv;
    }
    __syncthreads();

    if (tid < FF) {
        double r = 0.0;
        for (int s = 0; s < SS; s++) r += wwd[s] * (double)wfb[s*FF + tid];
        repr_out[(size_t)seq*FF + tid] = r;
    }

    // write relu(dil) to global: [seq][s][l][f]
    for (int i = tid; i < SS*LL*FF; i += ENC_THREADS) {
        int s = i / (LL*FF); int r = i % (LL*FF); int l = r / FF; int f = r % FF;
        float v = (l == 0) ? d1[f*SS+s] : (l == 1) ? d2[f*SS+s] : d3[f*SS+s];
        emb_out[(size_t)seq*(SS*LL*FF) + i] = fmaxf(v, 0.f);
    }
}

// ---------------- scores + top-k (fp64 scores) ----------------
__global__ void attn_topk_kernel(const unsigned char* __restrict__ mask)
{
    __shared__ double sc[HIS];
    const int bc = blockIdx.x, b = bc / CDD, tid = threadIdx.x;
    if (tid < HIS) {
        const double* cr = g_cdd_repr + (size_t)bc*FF;
        const double* hr = g_his_repr + (size_t)(b*HIS + tid)*FF;
        double s = 0.0;
        for (int f = 0; f < FF; f++) s += cr[f]*hr[f];
        if (mask[b*HIS + tid]) s = -1e300;
        sc[tid] = s;
    }
    __syncthreads();
    if (tid == 0) {
        unsigned long long used = 0ULL;
        for (int k = 0; k < KK; k++) {
            double best = -1e301; int bi = -1;
            for (int h = 0; h < HIS; h++) {
                if ((used >> h) & 1ULL) continue;
                if (sc[h] > best) { best = sc[h]; bi = h; }
            }
            used |= 1ULL << bi;
            g_topk[bc*KK + k] = bi;
        }
    }
}

// ---------------- fusion einsum ----------------
#define FUS_SMEM_FLOATS 18000
__global__ void __launch_bounds__(96)
fusion_kernel()
{
    extern __shared__ float sm[];
    float* cs = sm;          // cdd slice [s][l][f] 9000
    float* hs = sm + 9000;   // his slice 9000
    const int k = blockIdx.x, bc = blockIdx.y, b = bc / CDD;
    const int tid = threadIdx.x;
    const int hh = g_topk[bc*KK + k];
    const float* cp = g_cdd_emb + (size_t)bc*(SS*LL*FF);
    const float* hp = g_his_emb + (size_t)(b*HIS + hh)*(SS*LL*FF);
    for (int i = tid; i < SS*LL*FF; i += 96) { cs[i] = cp[i]; hs[i] = hp[i]; }
    __syncthreads();

    const float rsF = rsqrtf((float)FF);
    if (tid < 75) {                       // 3 l * 5 si * 5 ti tiles of 4x4
        int l = tid / 25, r = tid % 25, si = r / 5, ti = r % 5;
        int s0 = si*4, t0 = ti*4;
        float acc[4][4];
        #pragma unroll
        for (int i = 0; i < 4; i++)
            #pragma unroll
            for (int j = 0; j < 4; j++) acc[i][j] = 0.f;
        const float* cb = cs + l*FF;
        const float* hb = hs + l*FF;
        for (int f = 0; f < FF; f++) {
            float c0 = cb[(s0+0)*450+f], c1 = cb[(s0+1)*450+f],
                  c2 = cb[(s0+2)*450+f], c3 = cb[(s0+3)*450+f];
            float h0 = hb[(t0+0)*450+f], h1 = hb[(t0+1)*450+f],
                  h2 = hb[(t0+2)*450+f], h3 = hb[(t0+3)*450+f];
            acc[0][0]+=c0*h0; acc[0][1]+=c0*h1; acc[0][2]+=c0*h2; acc[0][3]+=c0*h3;
            acc[1][0]+=c1*h0; acc[1][1]+=c1*h1; acc[1][2]+=c1*h2; acc[1][3]+=c1*h3;
            acc[2][0]+=c2*h0; acc[2][1]+=c2*h1; acc[2][2]+=c2*h2; acc[2][3]+=c2*h3;
            acc[3][0]+=c3*h0; acc[3][1]+=c3*h1; acc[3][2]+=c3*h2; acc[3][3]+=c3*h3;
        }
        float* out = g_fusion + ((size_t)(bc*LL + l)*KK + k)*(SS*SS);
        #pragma unroll
        for (int i = 0; i < 4; i++)
            #pragma unroll
            for (int j = 0; j < 4; j++)
                out[(s0+i)*SS + (t0+j)] = acc[i][j] * rsF;
    }
}

// ---------------- conv3d-1 + relu + maxpool3 ----------------
// smem: sl[3][5][20][20]=6000 | wsm 2592 | arr 10368 | bsm 32
#define C3D1_SMEM_FLOATS (6000+2592+10368+32)
__global__ void __launch_bounds__(256)
c3d1_kernel(const float* __restrict__ w, const float* __restrict__ bias)
{
    extern __shared__ float sm[];
    float* sl  = sm;
    float* wsm = sm + 6000;
    float* arr = sm + 6000 + 2592;
    float* bsm = arr + 10368;
    const int pd = blockIdx.x, bc = blockIdx.y, tid = threadIdx.x;

    for (int i = tid; i < 32*3*27; i += 256) wsm[i] = w[i];
    if (tid < 32) bsm[tid] = bias[tid];
    const float* inb = g_fusion + (size_t)bc*(LL*KK*SS*SS);
    for (int i = tid; i < 6000; i += 256) {
        int ci = i / 2000, r = i % 2000, dd = r / 400, hw = r % 400;
        int d = 3*pd - 1 + dd;
        sl[i] = (d >= 0 && d < KK) ? inb[(ci*KK + d)*400 + hw] : 0.f;
    }
    __syncthreads();

    // phase1: per (co, dd, h) row of 18 w-outputs, relu, pool-w
    for (int t = tid; t < 32*3*18; t += 256) {
        int co = t / 54, r = t % 54, dd = r / 18, h = r % 18;
        float acc[18];
        float bv = bsm[co];
        #pragma unroll
        for (int x = 0; x < 18; x++) acc[x] = bv;
        for (int ci = 0; ci < 3; ci++) {
            #pragma unroll
            for (int kd = 0; kd < 3; kd++) {
                const float* slice = sl + (ci*5 + dd + kd)*400;
                #pragma unroll
                for (int kh = 0; kh < 3; kh++) {
                    int hr = h + kh - 1;
                    if (hr < 0 || hr >= 20) continue;
                    float rv[22]; rv[0] = 0.f; rv[21] = 0.f;
                    LOAD20(rv, slice + hr*20, 1);
                    const float* wp = wsm + (co*3 + ci)*27 + kd*9 + kh*3;
                    float w0 = wp[0], wa = wp[1], wb = wp[2];
                    #pragma unroll
                    for (int x = 0; x < 18; x++)
                        acc[x] += w0*rv[x] + wa*rv[x+1] + wb*rv[x+2];
                }
            }
        }
        #pragma unroll
        for (int pw = 0; pw < 6; pw++) {
            float m = fmaxf(fmaxf(acc[3*pw], acc[3*pw+1]), acc[3*pw+2]);
            arr[t*6 + pw] = fmaxf(m, 0.f);
        }
    }
    __syncthreads();

    // phase2: max over (dd, hh) pool window
    for (int t = tid; t < 32*36; t += 256) {
        int co = t / 36, r = t % 36, ph = r / 6, pw = r % 6;
        float m = 0.f;
        #pragma unroll
        for (int dd = 0; dd < 3; dd++)
            #pragma unroll
            for (int hh = 0; hh < 3; hh++)
                m = fmaxf(m, arr[((co*3 + dd)*18 + 3*ph + hh)*6 + pw]);
        g_pool1[((size_t)(bc*32 + co)*10 + pd)*36 + ph*6 + pw] = m;
    }
}

// ---------------- conv3d-2 + relu + maxpool3 ----------------
// smem: in 32*10*36=11520 | wsm 13824 | arr 1728 | bsm 16
#define C3D2_SMEM_FLOATS (11520+13824+1728+16)
__global__ void __launch_bounds__(256)
c3d2_kernel(const float* __restrict__ w, const float* __restrict__ bias)
{
    extern __shared__ float sm[];
    float* inb = sm;
    float* wsm = sm + 11520;
    float* arr = sm + 11520 + 13824;
    float* bsm = arr + 1728;
    const int bc = blockIdx.x, tid = threadIdx.x;

    const float* gin = g_pool1 + (size_t)bc*32*360;
    for (int i = tid; i < 11520; i += 256) inb[i] = gin[i];
    for (int i = tid; i < 16*32*27; i += 256) wsm[i] = w[i];
    if (tid < 16) bsm[tid] = bias[tid];
    __syncthreads();

    // phase1: per (co, d, h) row of 6 w-outputs (d 0..8, h 0..5)
    for (int t = tid; t < 16*9*6; t += 256) {
        int co = t / 54, r = t % 54, d = r / 6, h = r % 6;
        float acc[6];
        float bv = bsm[co];
        #pragma unroll
        for (int x = 0; x < 6; x++) acc[x] = bv;
        for (int ci = 0; ci < 32; ci++) {
            #pragma unroll
            for (int kd = 0; kd < 3; kd++) {
                int dr = d + kd - 1;
                if (dr < 0 || dr >= 10) continue;
                #pragma unroll
                for (int kh = 0; kh < 3; kh++) {
                    int hr = h + kh - 1;
                    if (hr < 0 || hr >= 6) continue;
                    const float* rowp = inb + (ci*10 + dr)*36 + hr*6;
                    float rv[8]; rv[0] = 0.f; rv[7] = 0.f;
                    #pragma unroll
                    for (int j = 0; j < 6; j++) rv[j+1] = rowp[j];
                    const float* wp = wsm + (co*32 + ci)*27 + kd*9 + kh*3;
                    float w0 = wp[0], wa = wp[1], wb = wp[2];
                    #pragma unroll
                    for (int x = 0; x < 6; x++)
                        acc[x] += w0*rv[x] + wa*rv[x+1] + wb*rv[x+2];
                }
            }
        }
        #pragma unroll
        for (int pw = 0; pw < 2; pw++) {
            float m = fmaxf(fmaxf(acc[3*pw], acc[3*pw+1]), acc[3*pw+2]);
            arr[t*2 + pw] = fmaxf(m, 0.f);
        }
    }
    __syncthreads();

    // phase2: pooled (co, pdo 0..2, ph 0..1, pw 0..1)
    for (int t = tid; t < 16*3*2*2; t += 256) {
        int co = t / 12, r = t % 12, pdo = r / 4, r2 = r % 4, ph = r2 / 2, pw = r2 % 2;
        float m = 0.f;
        #pragma unroll
        for (int dd = 0; dd < 3; dd++)
            #pragma unroll
            for (int hh = 0; hh < 3; hh++)
                m = fmaxf(m, arr[((co*9 + 3*pdo + dd)*6 + 3*ph + hh)*2 + pw]);
        g_pool2[(size_t)bc*192 + ((co*3 + pdo)*2 + ph)*2 + pw] = m;
    }
}

// ---------------- final linear + log_softmax (fp64) ----------------
__global__ void final_kernel(const float* __restrict__ ltr_w,
                             const float* __restrict__ ltr_b,
                             float* __restrict__ out)
{
    __shared__ double sc[Bq*CDD];
    __shared__ double lse[Bq];
    const int tid = threadIdx.x;
    if (tid < Bq*CDD) {
        const float* f = g_pool2 + (size_t)tid*192;
        double s = (double)ltr_b[0];
        for (int i = 0; i < 192; i++) s += (double)f[i]*(double)ltr_w[i];
        sc[tid] = s;
    }
    __syncthreads();
    if (tid < Bq) {
        double m = -1e300;
        for (int c = 0; c < CDD; c++) m = fmax(m, sc[tid*CDD + c]);
        double sum = 0.0;
        for (int c = 0; c < CDD; c++) sum += exp(sc[tid*CDD + c] - m);
        lse[tid] = m + log(sum);
    }
    __syncthreads();
    if (tid < Bq*CDD) out[tid] = (float)(sc[tid] - lse[tid/CDD]);
}

// ---------------- launch ----------------
extern "C" void kernel_launch(void* const* d_in, const int* in_sizes, int n_in,
                              void* d_out, int out_size)
{
    const int*   cand = (const int*)d_in[0];
    const int*   clk  = (const int*)d_in[1];
    const unsigned char* mask = (const unsigned char*)d_in[2];
    const float* emb  = (const float*)d_in[3];
    const float* w1   = (const float*)d_in[4];
    const float* b1   = (const float*)d_in[5];
    const float* w2   = (const float*)d_in[6];
    const float* b2   = (const float*)d_in[7];
    const float* w3   = (const float*)d_in[8];
    const float* b3   = (const float*)d_in[9];
    const float* lnw  = (const float*)d_in[10];
    const float* lnb  = (const float*)d_in[11];
    const float* qw   = (const float*)d_in[12];
    const float* ql   = (const float*)d_in[13];
    const float* c1w  = (const float*)d_in[14];
    const float* c1b  = (const float*)d_in[15];
    const float* c2w  = (const float*)d_in[16];
    const float* c2b  = (const float*)d_in[17];
    const float* ltrw = (const float*)d_in[18];
    const float* ltrb = (const float*)d_in[19];
    float* out = (float*)d_out;

    const int enc_smem  = ENC_SMEM_FLOATS  * 4;
    const int fus_smem  = FUS_SMEM_FLOATS  * 4;
    const int c3d1_smem = C3D1_SMEM_FLOATS * 4;
    const int c3d2_smem = C3D2_SMEM_FLOATS * 4;
    cudaFuncSetAttribute(encode_kernel, cudaFuncAttributeMaxDynamicSharedMemorySize, enc_smem);
    cudaFuncSetAttribute(fusion_kernel, cudaFuncAttributeMaxDynamicSharedMemorySize, fus_smem);
    cudaFuncSetAttribute(c3d1_kernel,   cudaFuncAttributeMaxDynamicSharedMemorySize, c3d1_smem);
    cudaFuncSetAttribute(c3d2_kernel,   cudaFuncAttributeMaxDynamicSharedMemorySize, c3d2_smem);

    encode_kernel<<<Bq*CDD, ENC_THREADS, enc_smem>>>(cand, emb, w1, b1, w2, b2, w3, b3,
                                                     lnw, lnb, qw, ql, 0);
    encode_kernel<<<Bq*HIS, ENC_THREADS, enc_smem>>>(clk, emb, w1, b1, w2, b2, w3, b3,
                                                     lnw, lnb, qw, ql, 1);
    attn_topk_kernel<<<Bq*CDD, 64>>>(mask);
    fusion_kernel<<<dim3(KK, Bq*CDD), 96, fus_smem>>>();
    c3d1_kernel<<<dim3(10, Bq*CDD), 256, c3d1_smem>>>(c1w, c1b);
    c3d2_kernel<<<Bq*CDD, 256, c3d2_smem>>>(c2w, c2b);
    final_kernel<<<1, 192>>>(ltrw, ltrb, out);
}

// round 4
// speedup vs baseline: 1.0579x; 1.0579x over previous
#include <cuda_runtime.h>
#include <math.h>

#define Bq  32
#define CDD 5
#define HIS 50
#define SS  20
#define EE  300
#define FF  150
#define KK  30
#define LL  3

// ---------------- scratch (static device globals; no allocs) ----------------
__device__ float  g_cdd_emb [Bq*CDD*LL*FF*SS];     // [bc][l][f][s]
__device__ float  g_his_emb [Bq*HIS*LL*FF*SS];     // [b*50+h][l][f][s]
__device__ double g_cdd_repr[Bq*CDD*FF];
__device__ double g_his_repr[Bq*HIS*FF];
__device__ int    g_topk    [Bq*CDD*KK];
__device__ float  g_fusion  [Bq*CDD*LL*KK*SS*SS];  // [bc][l][k][s][t]
__device__ float  g_pool1   [Bq*CDD*32*10*6*6];    // [bc][co][pd][ph][pw]
__device__ float  g_pool2   [Bq*CDD*192];          // [bc][co][d][h][w]

// load 20 consecutive smem floats via 5x LDS.128 into dst[off..off+19]
#define LOAD20(dst, src, off) { \
  const float4* _p = (const float4*)(src); \
  float4 _a=_p[0], _b=_p[1], _c=_p[2], _d=_p[3], _e=_p[4]; \
  (dst)[(off)+0]=_a.x; (dst)[(off)+1]=_a.y; (dst)[(off)+2]=_a.z; (dst)[(off)+3]=_a.w; \
  (dst)[(off)+4]=_b.x; (dst)[(off)+5]=_b.y; (dst)[(off)+6]=_b.z; (dst)[(off)+7]=_b.w; \
  (dst)[(off)+8]=_c.x; (dst)[(off)+9]=_c.y; (dst)[(off)+10]=_c.z; (dst)[(off)+11]=_c.w; \
  (dst)[(off)+12]=_d.x; (dst)[(off)+13]=_d.y; (dst)[(off)+14]=_d.z; (dst)[(off)+15]=_d.w; \
  (dst)[(off)+16]=_e.x; (dst)[(off)+17]=_e.y; (dst)[(off)+18]=_e.z; (dst)[(off)+19]=_e.w; }

// ---------------- encode: per-sequence fused conv stack + attention ---------
// dynamic smem (floats): xb 0..5999 | d1 6000 | d2 9000 | d3 12000 |
// mu 15000(20) | rs 15020(20) | lw 15040(60) | wwd 15104(double[20]=40 fl)
// wt 15160 (150*19 = 2850)   total 18010 floats = 72.0 KB
#define ENC_WT_OFF   15160
#define ENC_SMEM_FLOATS (ENC_WT_OFF + FF*19)
#define ENC_THREADS 160
#define CH 6   // channels per weight tile chunk (divides 150 and 300)

// LayerNorm over f for each s, stats in fp64.
__device__ __forceinline__ void ln_T(float* buf, float* mu, float* rs,
                                     const float* lnw, const float* lnb, int tid) {
    __syncthreads();
    if (tid < SS) {
        double m = 0.0;
        for (int f = 0; f < FF; f++) m += (double)buf[f*SS + tid];
        m *= (1.0/FF);
        double v = 0.0;
        for (int f = 0; f < FF; f++) { double d = (double)buf[f*SS + tid] - m; v += d*d; }
        v *= (1.0/FF);
        mu[tid] = (float)m;
        rs[tid] = (float)(1.0 / sqrt(v + 1e-5));
    }
    __syncthreads();
    if (tid < FF) {
        float w = lnw[tid], b = lnb[tid];
        #pragma unroll
        for (int s = 0; s < SS; s++)
            buf[tid*SS + s] = (buf[tid*SS + s] - mu[s]) * rs[s] * w + b;
    }
    __syncthreads();
}

// One dilated conv layer: in_buf [Cin][SS] smem -> out_buf [FF][SS] smem.
// Weights streamed through smem tile wt (coalesced global loads, conflict-free LDS).
template<int CIN, int DIL, int WSTRIDE>
__device__ __forceinline__ void conv_layer(const float* __restrict__ w,
                                           const float* __restrict__ bias,
                                           const float* in_buf, float* out_buf,
                                           float* wt, int tid)
{
    double accd[SS];
    float  accm[SS];
    if (tid < FF) {
        double bv = (double)bias[tid];
        #pragma unroll
        for (int s = 0; s < SS; s++) { accd[s] = bv; accm[s] = 0.f; }
    }
    int fold = 0;
    for (int c0 = 0; c0 < CIN; c0 += CH) {
        __syncthreads();                       // protect wt from previous chunk use
        for (int i = tid; i < FF*(CH*3); i += ENC_THREADS) {
            int f = i / (CH*3), j = i % (CH*3);
            wt[f*19 + j] = w[f*WSTRIDE + c0*3 + j];
        }
        __syncthreads();
        if (tid < FF) {
            float wreg[CH*3];
            #pragma unroll
            for (int j = 0; j < CH*3; j++) wreg[j] = wt[tid*19 + j];
            #pragma unroll
            for (int cc = 0; cc < CH; cc++) {
                float xv[SS + 2*DIL];
                #pragma unroll
                for (int z = 0; z < DIL; z++) { xv[z] = 0.f; xv[SS + DIL + z] = 0.f; }
                LOAD20(xv, in_buf + (c0+cc)*SS, DIL);
                float w0 = wreg[cc*3+0], wa = wreg[cc*3+1], wb = wreg[cc*3+2];
                #pragma unroll
                for (int s = 0; s < SS; s++)
                    accm[s] += w0*xv[s] + wa*xv[s+DIL] + wb*xv[s+2*DIL];
            }
            if (++fold == 4 || c0 + CH >= CIN) {
                #pragma unroll
                for (int s = 0; s < SS; s++) { accd[s] += (double)accm[s]; accm[s] = 0.f; }
                fold = 0;
            }
        }
    }
    if (tid < FF) {
        #pragma unroll
        for (int s = 0; s < SS; s++) out_buf[tid*SS + s] = (float)accd[s];
    }
}

__global__ void __launch_bounds__(ENC_THREADS, 3)
encode_kernel(const int* __restrict__ ids_all, const float* __restrict__ emb,
              const float* __restrict__ w1, const float* __restrict__ b1,
              const float* __restrict__ w2, const float* __restrict__ b2,
              const float* __restrict__ w3, const float* __restrict__ b3,
              const float* __restrict__ lnw, const float* __restrict__ lnb,
              const float* __restrict__ q_words, const float* __restrict__ q_levels,
              int is_his)
{
    extern __shared__ float sm[];
    float*  xb  = sm;            // [e][s]  6000
    float*  d1  = sm + 6000;     // [f][s]  3000
    float*  d2  = sm + 9000;
    float*  d3  = sm + 12000;
    float*  mu  = sm + 15000;
    float*  rs  = sm + 15020;
    float*  lw  = sm + 15040;    // [s][l] 60
    double* wwd = (double*)(sm + 15104); // [s] 20 doubles (8B aligned)
    float*  wt  = sm + ENC_WT_OFF;
    float*  wfb = xb;            // reuse xb after conv1: wf [s][f] 3000
    __shared__ int ids[SS];

    const int seq = blockIdx.x;
    const int tid = threadIdx.x;

    float*  emb_out  = is_his ? g_his_emb  : g_cdd_emb;
    double* repr_out = is_his ? g_his_repr : g_cdd_repr;

    if (tid < SS) ids[tid] = ids_all[seq*SS + tid];
    __syncthreads();
    for (int i = tid; i < SS*EE; i += ENC_THREADS) {
        int s = i / EE, e = i % EE;
        xb[e*SS + s] = emb[(size_t)ids[s]*EE + e];
    }
    __syncthreads();

    conv_layer<EE, 1, EE*3>(w1, b1, xb, d1, wt, tid);
    ln_T(d1, mu, rs, lnw, lnb, tid);
    conv_layer<FF, 2, FF*3>(w2, b2, d1, d2, wt, tid);
    ln_T(d2, mu, rs, lnw, lnb, tid);
    conv_layer<FF, 3, FF*3>(w3, b3, d2, d3, wt, tid);
    ln_T(d3, mu, rs, lnw, lnb, tid);

    const double inv_scale = 1.0 / sqrt((double)EE);

    // level attention: softmax over l per s (fp64 logits)
    if (tid < SS) {
        int s = tid;
        double l0 = 0.0, l1 = 0.0, l2 = 0.0;
        for (int f = 0; f < FF; f++) {
            double q = (double)q_levels[f];
            l0 += (double)fmaxf(d1[f*SS+s], 0.f) * q;
            l1 += (double)fmaxf(d2[f*SS+s], 0.f) * q;
            l2 += (double)fmaxf(d3[f*SS+s], 0.f) * q;
        }
        l0 *= inv_scale; l1 *= inv_scale; l2 *= inv_scale;
        double m = fmax(l0, fmax(l1, l2));
        double e0 = exp(l0-m), e1 = exp(l1-m), e2 = exp(l2-m);
        double inv = 1.0 / (e0+e1+e2);
        lw[s*3+0] = (float)(e0*inv); lw[s*3+1] = (float)(e1*inv); lw[s*3+2] = (float)(e2*inv);
    }
    __syncthreads();

    // wf[s][f]
    if (tid < FF) {
        #pragma unroll
        for (int s = 0; s < SS; s++) {
            float v = lw[s*3+0]*fmaxf(d1[tid*SS+s], 0.f)
                    + lw[s*3+1]*fmaxf(d2[tid*SS+s], 0.f)
                    + lw[s*3+2]*fmaxf(d3[tid*SS+s], 0.f);
            wfb[s*FF + tid] = v;
        }
    }
    __syncthreads();

    // word attention logits (fp64)
    if (tid < SS) {
        double g = 0.0;
        for (int f = 0; f < FF; f++) g += (double)wfb[tid*FF + f] * (double)q_words[f];
        wwd[tid] = g * inv_scale;
    }
    __syncthreads();
    if (tid == 0) {
        double m = -1e300;
        for (int s = 0; s < SS; s++) m = fmax(m, wwd[s]);
        double sum = 0.0;
        for (int s = 0; s < SS; s++) { double e = exp(wwd[s]-m); wwd[s] = e; sum += e; }
        double inv = 1.0 / sum;
        for (int s = 0; s < SS; s++) wwd[s] *= inv;
    }
    __syncthreads();

    if (tid < FF) {
        double r = 0.0;
        for (int s = 0; s < SS; s++) r += wwd[s] * (double)wfb[s*FF + tid];
        repr_out[(size_t)seq*FF + tid] = r;
    }

    // write relu(dil) to global in layout [seq][l][f][s] (d* are already [f][s])
    for (int i = tid; i < LL*FF*SS; i += ENC_THREADS) {
        int l = i / (FF*SS); int r = i % (FF*SS);
        float v = (l == 0) ? d1[r] : (l == 1) ? d2[r] : d3[r];
        emb_out[(size_t)seq*(LL*FF*SS) + i] = fmaxf(v, 0.f);
    }
}

// ---------------- scores + top-k (fp64 scores) ----------------
__global__ void attn_topk_kernel(const unsigned char* __restrict__ mask)
{
    __shared__ double sc[HIS];
    const int bc = blockIdx.x, b = bc / CDD, tid = threadIdx.x;
    if (tid < HIS) {
        const double* cr = g_cdd_repr + (size_t)bc*FF;
        const double* hr = g_his_repr + (size_t)(b*HIS + tid)*FF;
        double s = 0.0;
        for (int f = 0; f < FF; f++) s += cr[f]*hr[f];
        if (mask[b*HIS + tid]) s = -1e300;
        sc[tid] = s;
    }
    __syncthreads();
    if (tid == 0) {
        unsigned long long used = 0ULL;
        for (int k = 0; k < KK; k++) {
            double best = -1e301; int bi = -1;
            for (int h = 0; h < HIS; h++) {
                if ((used >> h) & 1ULL) continue;
                if (sc[h] > best) { best = sc[h]; bi = h; }
            }
            used |= 1ULL << bi;
            g_topk[bc*KK + k] = bi;
        }
    }
}

// ---------------- fusion einsum ([l][f][s] layout -> float4 LDS) ------------
#define FUS_SMEM_FLOATS 18000
__global__ void __launch_bounds__(96)
fusion_kernel()
{
    extern __shared__ float sm[];
    float* cs = sm;          // cdd slice [l][f][s] 9000
    float* hs = sm + 9000;   // his slice 9000
    const int k = blockIdx.x, bc = blockIdx.y, b = bc / CDD;
    const int tid = threadIdx.x;
    const int hh = g_topk[bc*KK + k];
    const float4* cp4 = (const float4*)(g_cdd_emb + (size_t)bc*(LL*FF*SS));
    const float4* hp4 = (const float4*)(g_his_emb + (size_t)(b*HIS + hh)*(LL*FF*SS));
    float4* cs4 = (float4*)cs;
    float4* hs4 = (float4*)hs;
    for (int i = tid; i < LL*FF*SS/4; i += 96) { cs4[i] = cp4[i]; hs4[i] = hp4[i]; }
    __syncthreads();

    const float rsF = rsqrtf((float)FF);
    if (tid < 75) {                       // 3 l * 5 si * 5 ti tiles of 4x4
        int l = tid / 25, r = tid % 25, si = r / 5, ti = r % 5;
        int s0 = si*4, t0 = ti*4;
        float acc[4][4];
        #pragma unroll
        for (int i = 0; i < 4; i++)
            #pragma unroll
            for (int j = 0; j < 4; j++) acc[i][j] = 0.f;
        const float* cb = cs + l*FF*SS;
        const float* hb = hs + l*FF*SS;
        for (int f = 0; f < FF; f++) {
            float4 c4 = *(const float4*)(cb + f*SS + s0);
            float4 h4 = *(const float4*)(hb + f*SS + t0);
            acc[0][0]+=c4.x*h4.x; acc[0][1]+=c4.x*h4.y; acc[0][2]+=c4.x*h4.z; acc[0][3]+=c4.x*h4.w;
            acc[1][0]+=c4.y*h4.x; acc[1][1]+=c4.y*h4.y; acc[1][2]+=c4.y*h4.z; acc[1][3]+=c4.y*h4.w;
            acc[2][0]+=c4.z*h4.x; acc[2][1]+=c4.z*h4.y; acc[2][2]+=c4.z*h4.z; acc[2][3]+=c4.z*h4.w;
            acc[3][0]+=c4.w*h4.x; acc[3][1]+=c4.w*h4.y; acc[3][2]+=c4.w*h4.z; acc[3][3]+=c4.w*h4.w;
        }
        float* out = g_fusion + ((size_t)(bc*LL + l)*KK + k)*(SS*SS);
        #pragma unroll
        for (int i = 0; i < 4; i++)
            #pragma unroll
            for (int j = 0; j < 4; j++)
                out[(s0+i)*SS + (t0+j)] = acc[i][j] * rsF;
    }
}

// ---------------- conv3d-1 + relu + maxpool3 ----------------
// smem: sl[3][5][20][20]=6000 | wsm 2592 | arr 10368 | bsm 32
#define C3D1_SMEM_FLOATS (6000+2592+10368+32)
__global__ void __launch_bounds__(256)
c3d1_kernel(const float* __restrict__ w, const float* __restrict__ bias)
{
    extern __shared__ float sm[];
    float* sl  = sm;
    float* wsm = sm + 6000;
    float* arr = sm + 6000 + 2592;
    float* bsm = arr + 10368;
    const int pd = blockIdx.x, bc = blockIdx.y, tid = threadIdx.x;

    for (int i = tid; i < 32*3*27; i += 256) wsm[i] = w[i];
    if (tid < 32) bsm[tid] = bias[tid];
    const float* inb = g_fusion + (size_t)bc*(LL*KK*SS*SS);
    for (int i = tid; i < 6000; i += 256) {
        int ci = i / 2000, r = i % 2000, dd = r / 400, hw = r % 400;
        int d = 3*pd - 1 + dd;
        sl[i] = (d >= 0 && d < KK) ? inb[(ci*KK + d)*400 + hw] : 0.f;
    }
    __syncthreads();

    // phase1: per (co, dd, h) row of 18 w-outputs, relu, pool-w
    for (int t = tid; t < 32*3*18; t += 256) {
        int co = t / 54, r = t % 54, dd = r / 18, h = r % 18;
        float acc[18];
        float bv = bsm[co];
        #pragma unroll
        for (int x = 0; x < 18; x++) acc[x] = bv;
        for (int ci = 0; ci < 3; ci++) {
            #pragma unroll
            for (int kd = 0; kd < 3; kd++) {
                const float* slice = sl + (ci*5 + dd + kd)*400;
                #pragma unroll
                for (int kh = 0; kh < 3; kh++) {
                    int hr = h + kh - 1;
                    if (hr < 0 || hr >= 20) continue;
                    float rv[22]; rv[0] = 0.f; rv[21] = 0.f;
                    LOAD20(rv, slice + hr*20, 1);
                    const float* wp = wsm + (co*3 + ci)*27 + kd*9 + kh*3;
                    float w0 = wp[0], wa = wp[1], wb = wp[2];
                    #pragma unroll
                    for (int x = 0; x < 18; x++)
                        acc[x] += w0*rv[x] + wa*rv[x+1] + wb*rv[x+2];
                }
            }
        }
        #pragma unroll
        for (int pw = 0; pw < 6; pw++) {
            float m = fmaxf(fmaxf(acc[3*pw], acc[3*pw+1]), acc[3*pw+2]);
            arr[t*6 + pw] = fmaxf(m, 0.f);
        }
    }
    __syncthreads();

    // phase2: max over (dd, hh) pool window
    for (int t = tid; t < 32*36; t += 256) {
        int co = t / 36, r = t % 36, ph = r / 6, pw = r % 6;
        float m = 0.f;
        #pragma unroll
        for (int dd = 0; dd < 3; dd++)
            #pragma unroll
            for (int hh = 0; hh < 3; hh++)
                m = fmaxf(m, arr[((co*3 + dd)*18 + 3*ph + hh)*6 + pw]);
        g_pool1[((size_t)(bc*32 + co)*10 + pd)*36 + ph*6 + pw] = m;
    }
}

// ---------------- conv3d-2 + relu + maxpool3 ----------------
// smem: in 32*10*36=11520 | wsm 13824 | arr 1728 | bsm 16
#define C3D2_SMEM_FLOATS (11520+13824+1728+16)
__global__ void __launch_bounds__(256)
c3d2_kernel(const float* __restrict__ w, const float* __restrict__ bias)
{
    extern __shared__ float sm[];
    float* inb = sm;
    float* wsm = sm + 11520;
    float* arr = sm + 11520 + 13824;
    float* bsm = arr + 1728;
    const int bc = blockIdx.x, tid = threadIdx.x;

    const float* gin = g_pool1 + (size_t)bc*32*360;
    for (int i = tid; i < 11520; i += 256) inb[i] = gin[i];
    for (int i = tid; i < 16*32*27; i += 256) wsm[i] = w[i];
    if (tid < 16) bsm[tid] = bias[tid];
    __syncthreads();

    // phase1: per (co, d, h) row of 6 w-outputs (d 0..8, h 0..5)
    for (int t = tid; t < 16*9*6; t += 256) {
        int co = t / 54, r = t % 54, d = r / 6, h = r % 6;
        float acc[6];
        float bv = bsm[co];
        #pragma unroll
        for (int x = 0; x < 6; x++) acc[x] = bv;
        for (int ci = 0; ci < 32; ci++) {
            #pragma unroll
            for (int kd = 0; kd < 3; kd++) {
                int dr = d + kd - 1;
                if (dr < 0 || dr >= 10) continue;
                #pragma unroll
                for (int kh = 0; kh < 3; kh++) {
                    int hr = h + kh - 1;
                    if (hr < 0 || hr >= 6) continue;
                    const float* rowp = inb + (ci*10 + dr)*36 + hr*6;
                    float rv[8]; rv[0] = 0.f; rv[7] = 0.f;
                    #pragma unroll
                    for (int j = 0; j < 6; j++) rv[j+1] = rowp[j];
                    const float* wp = wsm + (co*32 + ci)*27 + kd*9 + kh*3;
                    float w0 = wp[0], wa = wp[1], wb = wp[2];
                    #pragma unroll
                    for (int x = 0; x < 6; x++)
                        acc[x] += w0*rv[x] + wa*rv[x+1] + wb*rv[x+2];
                }
            }
        }
        #pragma unroll
        for (int pw = 0; pw < 2; pw++) {
            float m = fmaxf(fmaxf(acc[3*pw], acc[3*pw+1]), acc[3*pw+2]);
            arr[t*2 + pw] = fmaxf(m, 0.f);
        }
    }
    __syncthreads();

    // phase2: pooled (co, pdo 0..2, ph 0..1, pw 0..1)
    for (int t = tid; t < 16*3*2*2; t += 256) {
        int co = t / 12, r = t % 12, pdo = r / 4, r2 = r % 4, ph = r2 / 2, pw = r2 % 2;
        float m = 0.f;
        #pragma unroll
        for (int dd = 0; dd < 3; dd++)
            #pragma unroll
            for (int hh = 0; hh < 3; hh++)
                m = fmaxf(m, arr[((co*9 + 3*pdo + dd)*6 + 3*ph + hh)*2 + pw]);
        g_pool2[(size_t)bc*192 + ((co*3 + pdo)*2 + ph)*2 + pw] = m;
    }
}

// ---------------- final linear + log_softmax (fp64) ----------------
__global__ void final_kernel(const float* __restrict__ ltr_w,
                             const float* __restrict__ ltr_b,
                             float* __restrict__ out)
{
    __shared__ double sc[Bq*CDD];
    __shared__ double lse[Bq];
    const int tid = threadIdx.x;
    if (tid < Bq*CDD) {
        const float* f = g_pool2 + (size_t)tid*192;
        double s = (double)ltr_b[0];
        for (int i = 0; i < 192; i++) s += (double)f[i]*(double)ltr_w[i];
        sc[tid] = s;
    }
    __syncthreads();
    if (tid < Bq) {
        double m = -1e300;
        for (int c = 0; c < CDD; c++) m = fmax(m, sc[tid*CDD + c]);
        double sum = 0.0;
        for (int c = 0; c < CDD; c++) sum += exp(sc[tid*CDD + c] - m);
        lse[tid] = m + log(sum);
    }
    __syncthreads();
    if (tid < Bq*CDD) out[tid] = (float)(sc[tid] - lse[tid/CDD]);
}

// ---------------- launch ----------------
extern "C" void kernel_launch(void* const* d_in, const int* in_sizes, int n_in,
                              void* d_out, int out_size)
{
    const int*   cand = (const int*)d_in[0];
    const int*   clk  = (const int*)d_in[1];
    const unsigned char* mask = (const unsigned char*)d_in[2];
    const float* emb  = (const float*)d_in[3];
    const float* w1   = (const float*)d_in[4];
    const float* b1   = (const float*)d_in[5];
    const float* w2   = (const float*)d_in[6];
    const float* b2   = (const float*)d_in[7];
    const float* w3   = (const float*)d_in[8];
    const float* b3   = (const float*)d_in[9];
    const float* lnw  = (const float*)d_in[10];
    const float* lnb  = (const float*)d_in[11];
    const float* qw   = (const float*)d_in[12];
    const float* ql   = (const float*)d_in[13];
    const float* c1w  = (const float*)d_in[14];
    const float* c1b  = (const float*)d_in[15];
    const float* c2w  = (const float*)d_in[16];
    const float* c2b  = (const float*)d_in[17];
    const float* ltrw = (const float*)d_in[18];
    const float* ltrb = (const float*)d_in[19];
    float* out = (float*)d_out;

    const int enc_smem  = ENC_SMEM_FLOATS  * 4;
    const int fus_smem  = FUS_SMEM_FLOATS  * 4;
    const int c3d1_smem = C3D1_SMEM_FLOATS * 4;
    const int c3d2_smem = C3D2_SMEM_FLOATS * 4;
    cudaFuncSetAttribute(encode_kernel, cudaFuncAttributeMaxDynamicSharedMemorySize, enc_smem);
    cudaFuncSetAttribute(fusion_kernel, cudaFuncAttributeMaxDynamicSharedMemorySize, fus_smem);
    cudaFuncSetAttribute(c3d1_kernel,   cudaFuncAttributeMaxDynamicSharedMemorySize, c3d1_smem);
    cudaFuncSetAttribute(c3d2_kernel,   cudaFuncAttributeMaxDynamicSharedMemorySize, c3d2_smem);

    encode_kernel<<<Bq*CDD, ENC_THREADS, enc_smem>>>(cand, emb, w1, b1, w2, b2, w3, b3,
                                                     lnw, lnb, qw, ql, 0);
    encode_kernel<<<Bq*HIS, ENC_THREADS, enc_smem>>>(clk, emb, w1, b1, w2, b2, w3, b3,
                                                     lnw, lnb, qw, ql, 1);
    attn_topk_kernel<<<Bq*CDD, 64>>>(mask);
    fusion_kernel<<<dim3(KK, Bq*CDD), 96, fus_smem>>>();
    c3d1_kernel<<<dim3(10, Bq*CDD), 256, c3d1_smem>>>(c1w, c1b);
    c3d2_kernel<<<Bq*CDD, 256, c3d2_smem>>>(c2w, c2b);
    final_kernel<<<1, 192>>>(ltrw, ltrb, out);
}